// round 14
// baseline (speedup 1.0000x reference)
#include <cuda_runtime.h>
#include <math.h>

constexpr int T = 512, B = 32, DIN = 41, H = 800;
constexpr int UPB = 12;                 // units per block
constexpr int BPD = 67;                 // blocks per direction
constexpr int NBLK = 2 * BPD;           // 134 persistent blocks (1 wave)
constexpr int SXS = 52;                 // padded input K
constexpr int SWF  = 48 * 800;          // smem weight slab (floats)
constexpr int SWXF = 48 * SXS;
constexpr int SXF  = 32 * SXS;
typedef unsigned long long ull;

// ---------------- scratch ----------------
__device__ float4 g_ht[2][2][200][B];   // [phase][dir][k4][b] transposed h
__device__ float g_h1[T][B][2 * H];
__device__ float g_h2[T][B][2 * H];
__device__ float g_xs1[2][T][4 * H][B];
__device__ float g_Wp[2][4 * H][SXS];
__device__ float g_ang[T][B][3];
__device__ int   g_bar[2][2][T];        // [layer][dir][step]

// ---------------- helpers ----------------
__device__ __forceinline__ void ffma2(ull& d, ull a, ull b) {
    asm("fma.rn.f32x2 %0, %1, %2, %0;" : "+l"(d) : "l"(a), "l"(b));
}
__device__ __forceinline__ float hadd(ull v) {
    float lo, hi;
    asm("mov.b64 {%0,%1}, %2;" : "=f"(lo), "=f"(hi) : "l"(v));
    return lo + hi;
}
__device__ __forceinline__ float sigm(float x) { return 1.0f / (1.0f + expf(-x)); }
__device__ __forceinline__ void cpasync16(unsigned dst, const void* src) {
    asm volatile("cp.async.cg.shared.global [%0], [%1], 16;" :: "r"(dst), "l"(src));
}
#define CP_COMMIT() asm volatile("cp.async.commit_group;")
#define CP_WAIT(n)  asm volatile("cp.async.wait_group %0;" :: "n"(n))

// ---------------- init ----------------
__global__ void zero_kernel() {
    int i = blockIdx.x * blockDim.x + threadIdx.x;
    if (i < 2 * 2 * 200 * B * 4) ((float*)g_ht)[i] = 0.0f;
    if (i < 2 * 2 * T) ((int*)g_bar)[i] = 0;
}
__global__ void zero_state_only() {
    int i = blockIdx.x * blockDim.x + threadIdx.x;
    if (i < 2 * 2 * 200 * B * 4) ((float*)g_ht)[i] = 0.0f;
}

__global__ void prep_wp(const float* __restrict__ Wf, const float* __restrict__ Wb) {
    int i = blockIdx.x * blockDim.x + threadIdx.x;
    if (i >= 2 * 4 * H * SXS) return;
    int dir = i / (4 * H * SXS);
    int rem = i % (4 * H * SXS);
    int r = rem / SXS, k = rem % SXS;
    const float* W = dir ? Wb : Wf;
    ((float*)g_Wp)[i] = (k < DIN) ? W[r * DIN + k] : 0.0f;
}

// ---------------- persistent bi-LSTM: smem weights + direct-LDG h ring ------
// 134 blocks x 384 thr = 12 warps. Warp w -> (rg = w%6 rows-of-8, ks = w/6).
// h read straight from L2 (transposed layout, 1 contiguous LDG.128 per 4-k,
// 4-slot register prefetch ring). No staging, no cp.async, 2-3 syncs/step.
template <int LAYER>
__global__ void __launch_bounds__(384, 1) lstm_persist(
    const float* __restrict__ x,
    const float* __restrict__ Whh_f, const float* __restrict__ b_f,
    const float* __restrict__ Whh_b, const float* __restrict__ b_b)
{
    extern __shared__ float smem[];
    float* sw  = smem;                       // [48][800]
    float* swx = smem + SWF;                 // [48][52]
    float* sx  = swx + SWXF;                 // [32][52]
    ull*  sredU = (ull*)(sx + SXF);          // [2ks][48r][32b]

    const int tid  = threadIdx.x;
    const int w    = tid >> 5;
    const int lane = tid & 31;               // batch
    const int rg   = w % 6, ks = w / 6;

    const int blk  = blockIdx.x;
    const int dir  = (blk >= BPD);
    const int ublk = dir ? blk - BPD : blk;
    const int UB    = (800 - ublk * UPB < UPB) ? (800 - ublk * UPB) : UPB;
    const int ubase = ublk * UPB;

    const float* __restrict__ Whh = dir ? Whh_b : Whh_f;
    const float* __restrict__ bia = dir ? b_b : b_f;

    // ---- preload weights into smem (once, reused 512 steps) ----
    for (int i = tid; i < 48 * 200; i += 384) {
        int r = i / 200, kq = i - r * 200;
        int g = r / 12, ur = r - g * 12;
        if (ur >= UB) ur = UB - 1;
        float4 v = __ldg((const float4*)(Whh + (size_t)(g * H + ubase + ur) * H + kq * 4));
        *(float4*)(sw + r * 800 + kq * 4) = v;
    }
    if (LAYER == 0) {
        for (int i = tid; i < 48 * 13; i += 384) {
            int r = i / 13, kq = i - r * 13;
            int g = r / 12, ur = r - g * 12;
            if (ur >= UB) ur = UB - 1;
            float4 v = __ldg((const float4*)(&g_Wp[dir][g * H + ubase + ur][kq * 4]));
            *(float4*)(swx + r * SXS + kq * 4) = v;
        }
    }
    __syncthreads();

    const bool updact = (w < UB);
    const int  uu = updact ? w : 0;
    float bias_r[4];
#pragma unroll
    for (int g = 0; g < 4; g++)
        bias_r[g] = __ldg(&bia[g * H + ubase + uu]);
    float creg = 0.0f;

#define GSTEP(HV, QQ)                                                        \
    do {                                                                     \
        ull hlo_ = ((const ull*)&(HV))[0], hhi_ = ((const ull*)&(HV))[1];    \
        _Pragma("unroll")                                                    \
        for (int j_ = 0; j_ < 8; j_++) {                                     \
            float4 wv_ = *(const float4*)(wb + j_ * 800 + (QQ) * 4);         \
            ffma2(acc[j_], ((const ull*)&wv_)[0], hlo_);                     \
            ffma2(acc[j_], ((const ull*)&wv_)[1], hhi_);                     \
        }                                                                    \
    } while (0)

    for (int s = 0; s < T; s++) {
        const int t  = dir ? (T - 1 - s) : s;
        const int ph = s & 1;

        if (LAYER == 0) {
            for (int i = tid; i < 32 * SXS; i += 384) {
                int b = i / SXS, k = i - b * SXS;
                sx[i] = (k < DIN) ? __ldg(&x[(t * B + b) * DIN + k]) : 0.0f;
            }
            __syncthreads();   // sx ready before input-proj below
        }

        ull acc[8];
#pragma unroll
        for (int j = 0; j < 8; j++) acc[j] = 0;

        // ---- main dot: h direct from L2, 4-slot prefetch ring ----
        {
            const float4* hp = &g_ht[ph][dir][ks * 100][0] + lane;  // +32/k4
            const float* wb = sw + (rg * 8) * 800 + ks * 400;
            float4 r0 = __ldcg(hp);
            float4 r1 = __ldcg(hp + 32);
            float4 r2 = __ldcg(hp + 64);
            float4 r3;
            for (int q = 0; q < 100; q += 4) {
                r3 = (q + 3 < 100) ? __ldcg(hp + (q + 3) * 32) : r0;
                GSTEP(r0, q);
                if (q + 4 < 100) r0 = __ldcg(hp + (q + 4) * 32);
                GSTEP(r1, q + 1);
                if (q + 5 < 100) r1 = __ldcg(hp + (q + 5) * 32);
                GSTEP(r2, q + 2);
                if (q + 6 < 100) r2 = __ldcg(hp + (q + 6) * 32);
                GSTEP(r3, q + 3);
            }
        }

        if (LAYER == 0) {                          // input proj, split 24/28
            const float* hb2 = sx + lane * SXS;
            const int ka = ks ? 24 : 0, kb = ks ? 52 : 24;
            for (int k = ka; k < kb; k += 4) {
                float4 hv = *(const float4*)(hb2 + k);
                ull hlo = ((const ull*)&hv)[0], hhi = ((const ull*)&hv)[1];
#pragma unroll
                for (int j = 0; j < 8; j++) {
                    float4 wv = *(const float4*)(swx + (rg * 8 + j) * SXS + k);
                    ffma2(acc[j], ((const ull*)&wv)[0], hlo);
                    ffma2(acc[j], ((const ull*)&wv)[1], hhi);
                }
            }
        }

#pragma unroll
        for (int j = 0; j < 8; j++)
            sredU[(ks * 48 + rg * 8 + j) * 32 + lane] = acc[j];
        __syncthreads();

        if (updact) {
            const int ug = ubase + w;
            float e[4];
#pragma unroll
            for (int g = 0; g < 4; g++) {
                int r = g * 12 + w;
                e[g] = hadd(sredU[r * 32 + lane])
                     + hadd(sredU[(48 + r) * 32 + lane]) + bias_r[g];
                if (LAYER == 1)
                    e[g] += __ldg(&g_xs1[dir][t][g * H + ug][lane]);
            }
            float cn = sigm(e[1]) * creg + sigm(e[0]) * tanhf(e[2]);
            float hn = sigm(e[3]) * tanhf(cn);
            creg = cn;
            ((float*)&g_ht[ph ^ 1][dir][ug >> 2][lane])[ug & 3] = hn;
            if (LAYER == 0) g_h1[t][lane][dir * H + ug] = hn;
            else            g_h2[t][lane][dir * H + ug] = hn;
        }

        __syncthreads();
        if (s < T - 1) {
            if (tid == 0) {
                __threadfence();
                atomicAdd(&g_bar[LAYER][dir][s], 1);
                while (((volatile int*)g_bar[LAYER][dir])[s] < BPD) {}
                __threadfence();
            }
            __syncthreads();
        }
    }
#undef GSTEP
}

// ---------------- xs1 = Wih1 @ h1 : 256 thr, 4 rows x (2 t x 4 b) ----------
__global__ void __launch_bounds__(256, 1) xs1_gemm(
    const float* __restrict__ Wf, const float* __restrict__ Wb)
{
    extern __shared__ float shd[];
    const unsigned sbase = (unsigned)__cvta_generic_to_shared(shd);
    const int gt = blockIdx.x, tp = blockIdx.y, dir = blockIdx.z;
    const float* __restrict__ W = dir ? Wb : Wf;
    const int t0 = tp * 2;

    const int tid = threadIdx.x;
    const int rowg = tid >> 3, bq = tid & 7;    // rowg 0..31
    const int r0 = gt * 128 + rowg * 4;
    const float* wbase = W + (size_t)r0 * (2 * H);

    ull acc[32];                                 // [j<4 rows][c<8 = tq*4+i]
#pragma unroll
    for (int j = 0; j < 32; j++) acc[j] = 0;

#define XS_ISSUE(p, bsel)                                                        \
    do {                                                                         \
        for (int i2_ = tid; i2_ < 2560; i2_ += 256) {                            \
            int tq_ = i2_ / 1280, rem_ = i2_ - tq_ * 1280;                       \
            int b_ = rem_ / 40, kq_ = rem_ - b_ * 40;                            \
            cpasync16(sbase + (unsigned)((bsel) * 10496 + tq_ * 5248 + b_ * 164 + kq_ * 4) * 4u, \
                      &g_h1[t0 + tq_][b_][(p) * 160 + kq_ * 4]);                 \
        }                                                                        \
        CP_COMMIT();                                                             \
    } while (0)

    XS_ISSUE(0, 0);
    CP_WAIT(0); __syncthreads();
    int buf = 0;
    for (int p = 0; p < 10; p++) {
        if (p < 9) XS_ISSUE(p + 1, buf ^ 1);
        const float* shp = shd + buf * 10496;
        const int k0 = p * 160;
        for (int k = 0; k < 160; k += 4) {
            float4 hv[8];
#pragma unroll
            for (int tq = 0; tq < 2; tq++)
#pragma unroll
                for (int i = 0; i < 4; i++)
                    hv[tq * 4 + i] = *(const float4*)&shp[tq * 5248 + (bq + 8 * i) * 164 + k];
#pragma unroll
            for (int j = 0; j < 4; j++) {
                float4 wv = __ldg((const float4*)(wbase + j * (2 * H) + k0 + k));
                ull wlo = ((const ull*)&wv)[0], whi = ((const ull*)&wv)[1];
#pragma unroll
                for (int c = 0; c < 8; c++) {
                    ffma2(acc[j * 8 + c], wlo, ((const ull*)&hv[c])[0]);
                    ffma2(acc[j * 8 + c], whi, ((const ull*)&hv[c])[1]);
                }
            }
        }
        CP_WAIT(0); __syncthreads();
        buf ^= 1;
    }
#undef XS_ISSUE
#pragma unroll
    for (int j = 0; j < 4; j++)
#pragma unroll
        for (int tq = 0; tq < 2; tq++)
#pragma unroll
            for (int i = 0; i < 4; i++)
                g_xs1[dir][t0 + tq][r0 + j][bq + 8 * i] = hadd(acc[j * 8 + tq * 4 + i]);
}

// ---------------- logits -> softmax-folded atan2 -> angles ----------------
__global__ void __launch_bounds__(640) logits_angles(
    const float* __restrict__ Wl, const float* __restrict__ bl,
    const float* __restrict__ alphabet)
{
    const int t = blockIdx.x, tid = threadIdx.x;
    __shared__ float sl[32][21];
    __shared__ float ssin[20][3], scos[20][3];

    if (tid < 60) {
        int a = tid / 3, j = tid % 3;
        float v = alphabet[tid];
        ssin[a][j] = sinf(v); scos[a][j] = cosf(v);
    }
    {
        int a = tid >> 5, b = tid & 31;
        float acc = 0.0f;
        for (int k = 0; k < 2 * H; k += 4) {
            float4 hv = __ldg((const float4*)&g_h2[t][b][k]);
            float4 wv = __ldg((const float4*)&Wl[a * 2 * H + k]);
            acc += hv.x * wv.x + hv.y * wv.y + hv.z * wv.z + hv.w * wv.w;
        }
        sl[b][a] = acc + __ldg(&bl[a]);
    }
    __syncthreads();

    if (tid < 32) {
        int b = tid;
        float m = -1e30f;
#pragma unroll
        for (int a = 0; a < 20; a++) m = fmaxf(m, sl[b][a]);
        float ys[3] = {0, 0, 0}, xc[3] = {0, 0, 0};
#pragma unroll
        for (int a = 0; a < 20; a++) {
            float e = expf(sl[b][a] - m);
#pragma unroll
            for (int j = 0; j < 3; j++) { ys[j] += e * ssin[a][j]; xc[j] += e * scos[a][j]; }
        }
#pragma unroll
        for (int j = 0; j < 3; j++) g_ang[t][b][j] = atan2f(ys[j], xc[j]);
    }
}

// ---------------- NeRF coordinate extension ----------------
__global__ void coord_scan_kernel(float* __restrict__ out)
{
    const int b = threadIdx.x;
    const float rl[3] = {1.458f, 1.525f, 1.33f};
    const float th[3] = {2.124f, 1.941f, 2.028f};
    float rct[3], rst[3];
#pragma unroll
    for (int j = 0; j < 3; j++) { rct[j] = rl[j] * cosf(th[j]); rst[j] = rl[j] * sinf(th[j]); }

    float ax = 0.f, ay = 0.f, az = 0.f;
    float bx = 1.458f, by = 0.f, bz = 0.f;
    float cx = 2.f, cy = 1.f, cz = 0.f;

    for (int n = 0; n < 3 * T; n++) {
        int tt = n / 3, j = n - 3 * tt;
        float phi = g_ang[tt][b][j];
        float bcx = cx - bx, bcy = cy - by, bcz = cz - bz;
        float inv = rsqrtf(bcx * bcx + bcy * bcy + bcz * bcz);
        bcx *= inv; bcy *= inv; bcz *= inv;
        float abx = bx - ax, aby = by - ay, abz = bz - az;
        float nx = aby * bcz - abz * bcy;
        float ny = abz * bcx - abx * bcz;
        float nz = abx * bcy - aby * bcx;
        inv = rsqrtf(nx * nx + ny * ny + nz * nz);
        nx *= inv; ny *= inv; nz *= inv;
        float mx = ny * bcz - nz * bcy;
        float my = nz * bcx - nx * bcz;
        float mz = nx * bcy - ny * bcx;
        float sphi, cphi;
        __sincosf(phi, &sphi, &cphi);
        float dx = cx - rct[j] * bcx + rst[j] * (cphi * mx + sphi * nx);
        float dy = cy - rct[j] * bcy + rst[j] * (cphi * my + sphi * ny);
        float dz = cz - rct[j] * bcz + rst[j] * (cphi * mz + sphi * nz);
        float* o = out + (n * B + b) * 3;
        o[0] = dx; o[1] = dy; o[2] = dz;
        ax = bx; ay = by; az = bz;
        bx = cx; by = cy; bz = cz;
        cx = dx; cy = dy; cz = dz;
    }
}

// ---------------- launch (8 graph nodes) ----------------
extern "C" void kernel_launch(void* const* d_in, const int* in_sizes, int n_in,
                              void* d_out, int out_size)
{
    const float* x      = (const float*)d_in[0];
    const float* Wih_f0 = (const float*)d_in[1];
    const float* Whh_f0 = (const float*)d_in[2];
    const float* b_f0   = (const float*)d_in[3];
    const float* Wih_b0 = (const float*)d_in[4];
    const float* Whh_b0 = (const float*)d_in[5];
    const float* b_b0   = (const float*)d_in[6];
    const float* Wih_f1 = (const float*)d_in[7];
    const float* Whh_f1 = (const float*)d_in[8];
    const float* b_f1   = (const float*)d_in[9];
    const float* Wih_b1 = (const float*)d_in[10];
    const float* Whh_b1 = (const float*)d_in[11];
    const float* b_b1   = (const float*)d_in[12];
    const float* Wl     = (const float*)d_in[13];
    const float* bl     = (const float*)d_in[14];
    const float* alpha  = (const float*)d_in[15];
    float* out = (float*)d_out;

    // smem: weights + x + reduction = 194,816 B
    const int smem_rec = (SWF + SWXF + SXF) * (int)sizeof(float) + 2 * 48 * 32 * (int)sizeof(ull);
    const int smem_xs1 = 2 * 10496 * (int)sizeof(float);    // 83,968 B
    cudaFuncSetAttribute(lstm_persist<0>, cudaFuncAttributeMaxDynamicSharedMemorySize, smem_rec);
    cudaFuncSetAttribute(lstm_persist<1>, cudaFuncAttributeMaxDynamicSharedMemorySize, smem_rec);
    cudaFuncSetAttribute(xs1_gemm, cudaFuncAttributeMaxDynamicSharedMemorySize, smem_xs1);

    prep_wp<<<1300, 256>>>(Wih_f0, Wih_b0);
    zero_kernel<<<400, 256>>>();
    lstm_persist<0><<<NBLK, 384, smem_rec>>>(x, Whh_f0, b_f0, Whh_b0, b_b0);
    xs1_gemm<<<dim3(25, 256, 2), 256, smem_xs1>>>(Wih_f1, Wih_b1);
    zero_state_only<<<400, 256>>>();
    lstm_persist<1><<<NBLK, 384, smem_rec>>>(nullptr, Whh_f1, b_f1, Whh_b1, b_b1);
    logits_angles<<<T, 640>>>(Wl, bl, alpha);
    coord_scan_kernel<<<1, 32>>>(out);
}